// round 6
// baseline (speedup 1.0000x reference)
#include <cuda_runtime.h>

// ---------------------------------------------------------------------------
// SplitPool, round 5: 2-launch pipeline, single-wave balanced pool.
//   1. setup_kernel : block 0 -> shfl-scan chunk_size, per-chunk dest slot +
//                     1/count; blocks 1..N -> zero d_out.
//   2. pool_kernel  : warp-autonomous streaming reduction. Grid sized to
//                     exactly one wave (SMs x 6 blocks, launch_bounds-forced);
//                     each warp owns one contiguous row range (perfect
//                     balance, no wave-2 tail). Pre-scaled atomicAdd straight
//                     into d_out.
// ---------------------------------------------------------------------------

#define DIM 128
#define DIM4 (DIM / 4)
#define MAX_CHUNKS 8192
#define MAX_B 64
#define BLOCKS_PER_SM 6

__device__ int   g_chunk_start[MAX_CHUNKS + 1];  // row offset of each chunk
__device__ int   g_dest[MAX_CHUNKS];             // output float offset, -1 = dropped
__device__ float g_inv[MAX_CHUNKS];              // 1 / max(count, 1)

// ---------------------------------------------------------------------------
// Kernel 1: setup. Block 0: scan + chunk metadata. Blocks >=1: zero output.
// ---------------------------------------------------------------------------
__global__ __launch_bounds__(1024) void setup_kernel(
    const int* __restrict__ cs, int n_chunks,
    const int* __restrict__ np, int B, int P,
    float* __restrict__ out, int out_f4) {

    if (blockIdx.x > 0) {
        float4* o4 = reinterpret_cast<float4*>(out);
        const float4 z = make_float4(0.f, 0.f, 0.f, 0.f);
        for (int i = (blockIdx.x - 1) * blockDim.x + threadIdx.x; i < out_f4;
             i += (gridDim.x - 1) * blockDim.x)
            o4[i] = z;
        return;
    }

    __shared__ int warp_pref[32];
    __shared__ int s_pool[MAX_B + 1];
    __shared__ int s_np[MAX_B];

    const int t = threadIdx.x;
    const int lane = t & 31;
    const int w = t >> 5;
    const int per = (n_chunks + 1023) >> 10;   // <= 8 for MAX_CHUNKS=8192

    int v[8];
    int tot = 0;
    #pragma unroll
    for (int k = 0; k < 8; k++) {
        int idx = t * per + k;
        int val = (k < per && idx < n_chunks) ? cs[idx] : 0;
        v[k] = val;
        tot += val;
    }

    // inclusive warp scan of per-thread totals
    int inc = tot;
    #pragma unroll
    for (int off = 1; off < 32; off <<= 1) {
        int n = __shfl_up_sync(0xffffffffu, inc, off);
        if (lane >= off) inc += n;
    }
    if (lane == 31) warp_pref[w] = inc;
    if (t < B) s_np[t] = np[t];
    __syncthreads();

    if (w == 0) {
        int ws = warp_pref[lane];
        #pragma unroll
        for (int off = 1; off < 32; off <<= 1) {
            int n = __shfl_up_sync(0xffffffffu, ws, off);
            if (lane >= off) ws += n;
        }
        warp_pref[lane] = ws;   // inclusive scan of warp sums
    }
    __syncthreads();

    int pref = inc - tot + (w > 0 ? warp_pref[w - 1] : 0);  // exclusive prefix
    #pragma unroll
    for (int k = 0; k < 8; k++) {
        int idx = t * per + k;
        if (k < per && idx < n_chunks) {
            g_chunk_start[idx] = pref;
            pref += v[k];
        }
    }
    if (t == 1023) g_chunk_start[n_chunks] = warp_pref[31];

    if (t == 0) {
        int acc = 0;
        for (int i = 0; i < B; i++) { s_pool[i] = acc; acc += s_np[i] + 1; }
        s_pool[B] = acc;
    }
    __syncthreads();

    // per-chunk destination + inverse count
    #pragma unroll
    for (int k = 0; k < 8; k++) {
        int c = t * per + k;
        if (k >= per || c >= n_chunks) break;
        int i = 0;
        while (i < B - 1 && s_pool[i + 1] <= c) i++;
        int peak = c - s_pool[i];
        bool valid = peak < s_np[i];
        g_dest[c] = valid ? (i * P + peak) * DIM : -1;
        g_inv[c]  = 1.0f / (float)max(v[k], 1);
    }
}

// ---------------------------------------------------------------------------
// Kernel 2: warp-autonomous streaming reduction, single wave.
// Each warp owns rows [gw*rpw, (gw+1)*rpw); lane = float4 column group.
// 4 independent in-flight loads per iter (MLP), 2 accumulators (reg savings).
// Per segment: 4 pre-scaled atomicAdds per lane directly into the output.
// ---------------------------------------------------------------------------
__global__ __launch_bounds__(256, BLOCKS_PER_SM)
void pool_kernel(const float* __restrict__ x, float* __restrict__ out,
                 int n_chunks, int total_rows, int rpw) {
    const int gw = (blockIdx.x * blockDim.x + threadIdx.x) >> 5;
    const int lane = threadIdx.x & 31;
    const int r0 = gw * rpw;
    if (r0 >= total_rows) return;
    const int r_end = min(r0 + rpw, total_rows);

    // binary search: largest chunk c with g_chunk_start[c] <= r0
    int lo = 0, hi = n_chunks - 1;
    while (lo < hi) {
        int mid = (lo + hi + 1) >> 1;
        if (g_chunk_start[mid] <= r0) lo = mid; else hi = mid - 1;
    }
    int c = lo;

    const float4* __restrict__ xv = reinterpret_cast<const float4*>(x);
    int s = r0;

    while (s < r_end) {
        const int e = min(g_chunk_start[c + 1], r_end);

        float4 a0 = make_float4(0.f, 0.f, 0.f, 0.f);
        float4 a1 = a0;

        int r = s;
        for (; r + 4 <= e; r += 4) {
            float4 v0 = __ldcs(&xv[(long long)(r + 0) * DIM4 + lane]);
            float4 v1 = __ldcs(&xv[(long long)(r + 1) * DIM4 + lane]);
            float4 v2 = __ldcs(&xv[(long long)(r + 2) * DIM4 + lane]);
            float4 v3 = __ldcs(&xv[(long long)(r + 3) * DIM4 + lane]);
            a0.x += v0.x; a0.y += v0.y; a0.z += v0.z; a0.w += v0.w;
            a1.x += v1.x; a1.y += v1.y; a1.z += v1.z; a1.w += v1.w;
            a0.x += v2.x; a0.y += v2.y; a0.z += v2.z; a0.w += v2.w;
            a1.x += v3.x; a1.y += v3.y; a1.z += v3.z; a1.w += v3.w;
        }
        for (; r < e; r++) {
            float4 v0 = __ldcs(&xv[(long long)r * DIM4 + lane]);
            a0.x += v0.x; a0.y += v0.y; a0.z += v0.z; a0.w += v0.w;
        }

        a0.x += a1.x; a0.y += a1.y; a0.z += a1.z; a0.w += a1.w;

        const int dest = g_dest[c];
        if (dest >= 0) {
            const float inv = g_inv[c];
            float* o = out + dest + lane * 4;
            atomicAdd(o + 0, a0.x * inv);
            atomicAdd(o + 1, a0.y * inv);
            atomicAdd(o + 2, a0.z * inv);
            atomicAdd(o + 3, a0.w * inv);
        }

        s = e;
        c++;
    }
}

// ---------------------------------------------------------------------------
// Launch
// ---------------------------------------------------------------------------
extern "C" void kernel_launch(void* const* d_in, const int* in_sizes, int n_in,
                              void* d_out, int out_size) {
    const float* x       = (const float*)d_in[0];
    const int*   cs      = (const int*)d_in[1];
    const int*   n_peaks = (const int*)d_in[2];

    const int n_chunks   = in_sizes[1];
    const int B          = in_sizes[2];
    const int total_rows = in_sizes[0] / DIM;
    const int P          = out_size / (B * DIM);   // max_n_peaks

    // 1. setup: block 0 scans + builds chunk metadata; blocks 1..64 zero out.
    setup_kernel<<<65, 1024>>>(cs, n_chunks, n_peaks, B, P,
                               (float*)d_out, out_size / 4);

    // 2. pool: exactly one wave. SM count queried host-side (capture-safe,
    //    no stream work, no allocation).
    int sms = 148, dev = 0;
    cudaGetDevice(&dev);
    cudaDeviceGetAttribute(&sms, cudaDevAttrMultiProcessorCount, dev);
    const int nblk = sms * BLOCKS_PER_SM;
    const int n_warps = nblk * (256 / 32);
    const int rpw = (total_rows + n_warps - 1) / n_warps;  // rows per warp
    pool_kernel<<<nblk, 256>>>(x, (float*)d_out, n_chunks, total_rows, rpw);
}

// round 11
// speedup vs baseline: 1.0396x; 1.0396x over previous
#include <cuda_runtime.h>

// ---------------------------------------------------------------------------
// SplitPool, round 10: 2-launch pipeline (proven R5 skeleton), pool with
// BLOCK-INTERLEAVED row assignment for DRAM row-buffer locality.
//   1. setup_kernel : block 0 -> shfl-scan chunk_size, per-chunk dest slot +
//                     1/count; blocks 1..N -> zero d_out.
//   2. pool_kernel  : each block owns a contiguous region; warp w reads rows
//                     {base+4w..base+4w+3} stepping 32 -> the block emits
//                     dense 16KB contiguous bursts (912 streams instead of
//                     7300). Warp-private segment accumulation, pre-scaled
//                     atomicAdd straight into d_out. No smem, no block sync.
// ---------------------------------------------------------------------------

#define DIM 128
#define DIM4 (DIM / 4)
#define MAX_CHUNKS 8192
#define MAX_B 64
#define BLOCKS_PER_SM 6
#define THREADS 256

__device__ int   g_cs[MAX_CHUNKS + 2];   // exclusive row offsets (chunk starts)
__device__ int   g_dest[MAX_CHUNKS];     // output float offset, -1 = dropped
__device__ float g_inv[MAX_CHUNKS];      // 1 / max(count, 1)

// ---------------------------------------------------------------------------
// Kernel 1: setup. Block 0: scan + chunk metadata. Blocks >=1: zero output.
// (unchanged from the passing R5 kernel, modulo array rename)
// ---------------------------------------------------------------------------
__global__ __launch_bounds__(1024) void setup_kernel(
    const int* __restrict__ cs, int n_chunks,
    const int* __restrict__ np, int B, int P,
    float* __restrict__ out, int out_f4) {

    if (blockIdx.x > 0) {
        float4* o4 = reinterpret_cast<float4*>(out);
        const float4 z = make_float4(0.f, 0.f, 0.f, 0.f);
        for (int i = (blockIdx.x - 1) * blockDim.x + threadIdx.x; i < out_f4;
             i += (gridDim.x - 1) * blockDim.x)
            o4[i] = z;
        return;
    }

    __shared__ int warp_pref[32];
    __shared__ int s_pool[MAX_B + 1];
    __shared__ int s_np[MAX_B];

    const int t = threadIdx.x;
    const int lane = t & 31;
    const int w = t >> 5;
    const int per = (n_chunks + 1023) >> 10;   // <= 8 for MAX_CHUNKS=8192

    int v[8];
    int tot = 0;
    #pragma unroll
    for (int k = 0; k < 8; k++) {
        int idx = t * per + k;
        int val = (k < per && idx < n_chunks) ? cs[idx] : 0;
        v[k] = val;
        tot += val;
    }

    // inclusive warp scan of per-thread totals
    int inc = tot;
    #pragma unroll
    for (int off = 1; off < 32; off <<= 1) {
        int n = __shfl_up_sync(0xffffffffu, inc, off);
        if (lane >= off) inc += n;
    }
    if (lane == 31) warp_pref[w] = inc;
    if (t < B) s_np[t] = np[t];
    __syncthreads();

    if (w == 0) {
        int ws = warp_pref[lane];
        #pragma unroll
        for (int off = 1; off < 32; off <<= 1) {
            int n = __shfl_up_sync(0xffffffffu, ws, off);
            if (lane >= off) ws += n;
        }
        warp_pref[lane] = ws;   // inclusive scan of warp sums
    }
    __syncthreads();

    int pref = inc - tot + (w > 0 ? warp_pref[w - 1] : 0);  // exclusive prefix
    #pragma unroll
    for (int k = 0; k < 8; k++) {
        int idx = t * per + k;
        if (k < per && idx < n_chunks) {
            g_cs[idx] = pref;
            pref += v[k];
        }
    }
    if (t == 1023) {
        g_cs[n_chunks] = warp_pref[31];
        g_cs[n_chunks + 1] = 0x7fffffff;   // sentinel
    }

    if (t == 0) {
        int acc = 0;
        for (int i = 0; i < B; i++) { s_pool[i] = acc; acc += s_np[i] + 1; }
        s_pool[B] = acc;
    }
    __syncthreads();

    // per-chunk destination + inverse count
    #pragma unroll
    for (int k = 0; k < 8; k++) {
        int c = t * per + k;
        if (k >= per || c >= n_chunks) break;
        int i = 0;
        while (i < B - 1 && s_pool[i + 1] <= c) i++;
        int peak = c - s_pool[i];
        bool valid = peak < s_np[i];
        g_dest[c] = valid ? (i * P + peak) * DIM : -1;
        g_inv[c]  = 1.0f / (float)max(v[k], 1);
    }
}

// ---------------------------------------------------------------------------
// Kernel 2 body: block-interleaved streaming segment reduction.
// Warp w processes rows {r0+4w..r0+4w+3}, {r0+4w+32..}, ... within the
// block's contiguous region. Rows visited in increasing order -> chunk index
// c only advances. Flush = 4 pre-scaled atomicAdds per lane into d_out.
// ---------------------------------------------------------------------------
template <bool TAIL>
__device__ __forceinline__ void pool_region(const float4* __restrict__ xv,
                                            float* __restrict__ out,
                                            int my_first, int region_end,
                                            int n_chunks, int lane) {
    // binary search: largest chunk c with g_cs[c] <= my_first
    int lo = 0, hi = n_chunks - 1;
    while (lo < hi) {
        int mid = (lo + hi + 1) >> 1;
        if (__ldg(&g_cs[mid]) <= my_first) lo = mid; else hi = mid - 1;
    }
    int c = lo;
    int cend = __ldg(&g_cs[c + 1]);

    float4 acc = make_float4(0.f, 0.f, 0.f, 0.f);

    auto flush = [&]() {
        const int dest = __ldg(&g_dest[c]);
        if (dest >= 0) {
            const float inv = __ldg(&g_inv[c]);
            float* o = out + dest + lane * 4;
            atomicAdd(o + 0, acc.x * inv);
            atomicAdd(o + 1, acc.y * inv);
            atomicAdd(o + 2, acc.z * inv);
            atomicAdd(o + 3, acc.w * inv);
        }
        acc = make_float4(0.f, 0.f, 0.f, 0.f);
    };
    auto advance = [&](int rr) {
        do { c++; cend = __ldg(&g_cs[c + 1]); } while (cend <= rr);
    };

    for (int rb = my_first; rb < region_end; rb += 32) {
        const bool f1 = TAIL ? (rb + 1 < region_end) : true;
        const bool f2 = TAIL ? (rb + 2 < region_end) : true;
        const bool f3 = TAIL ? (rb + 3 < region_end) : true;

        const long long base = (long long)rb * DIM4 + lane;
        float4 v0, v1, v2, v3;
        v0 = __ldcs(xv + base);
        if (f1) v1 = __ldcs(xv + base + DIM4);
        if (f2) v2 = __ldcs(xv + base + 2 * DIM4);
        if (f3) v3 = __ldcs(xv + base + 3 * DIM4);

        if (rb >= cend) { flush(); advance(rb); }
        acc.x += v0.x; acc.y += v0.y; acc.z += v0.z; acc.w += v0.w;
        if (f1) {
            if (rb + 1 >= cend) { flush(); advance(rb + 1); }
            acc.x += v1.x; acc.y += v1.y; acc.z += v1.z; acc.w += v1.w;
        }
        if (f2) {
            if (rb + 2 >= cend) { flush(); advance(rb + 2); }
            acc.x += v2.x; acc.y += v2.y; acc.z += v2.z; acc.w += v2.w;
        }
        if (f3) {
            if (rb + 3 >= cend) { flush(); advance(rb + 3); }
            acc.x += v3.x; acc.y += v3.y; acc.z += v3.z; acc.w += v3.w;
        }
    }
    flush();  // last chunk partial
}

__global__ __launch_bounds__(THREADS, BLOCKS_PER_SM)
void pool_kernel(const float* __restrict__ x, float* __restrict__ out,
                 int n_chunks, int total_rows, int rpb) {
    const int w = threadIdx.x >> 5;
    const int lane = threadIdx.x & 31;
    const int r0 = blockIdx.x * rpb;
    if (r0 >= total_rows) return;

    const int my_first = r0 + w * 4;
    if (my_first >= total_rows) return;

    const float4* xv = reinterpret_cast<const float4*>(x);

    if (r0 + rpb <= total_rows) {
        pool_region<false>(xv, out, my_first, r0 + rpb, n_chunks, lane);
    } else {
        pool_region<true>(xv, out, my_first, total_rows, n_chunks, lane);
    }
}

// ---------------------------------------------------------------------------
// Launch
// ---------------------------------------------------------------------------
extern "C" void kernel_launch(void* const* d_in, const int* in_sizes, int n_in,
                              void* d_out, int out_size) {
    const float* x       = (const float*)d_in[0];
    const int*   cs      = (const int*)d_in[1];
    const int*   n_peaks = (const int*)d_in[2];

    const int n_chunks   = in_sizes[1];
    const int B          = in_sizes[2];
    const int total_rows = in_sizes[0] / DIM;
    const int P          = out_size / (B * DIM);   // max_n_peaks

    // 1. setup: block 0 scans + builds chunk metadata; blocks 1..64 zero out.
    setup_kernel<<<65, 1024>>>(cs, n_chunks, n_peaks, B, P,
                               (float*)d_out, out_size / 4);

    // 2. pool: single wave, contiguous region per block (multiple of 32 rows).
    int sms = 148, dev = 0;
    cudaGetDevice(&dev);
    cudaDeviceGetAttribute(&sms, cudaDevAttrMultiProcessorCount, dev);
    const int nblk = sms * BLOCKS_PER_SM;
    const int rpb = ((total_rows + nblk * 32 - 1) / (nblk * 32)) * 32;
    pool_kernel<<<nblk, THREADS>>>(x, (float*)d_out, n_chunks, total_rows, rpb);
}